// round 6
// baseline (speedup 1.0000x reference)
#include <cuda_runtime.h>
#include <cuda_bf16.h>
#include <cstdint>
#include <cstddef>

#define NMAX 50000
#define EMAX 800000
#define DF   128
#define NC   64

// ---------------- scratch (static device globals; no allocation) -------------
__device__ float g_dinv[NMAX];
__device__ float g_buf[(size_t)NMAX * DF];
__device__ int   g_cnt[NMAX];
__device__ int   g_scan[NMAX];
__device__ int   g_bsum[128];
__device__ int   g_off[NMAX + 1];
__device__ int   g_cur[NMAX];
__device__ int   g_csr[EMAX];
__device__ int   g_idx64;
// W^T split to bf16 hi/lo, padded layout [n*136 + k] halves: [layer][hi/lo]
__device__ __align__(16) unsigned char g_wt[3][2][128 * 272];

// ---------------- edge utils ---------------------------------------------------
__device__ __forceinline__ int edge_at(const void* e, long long i, int is64) {
    return is64 ? (int)((const long long*)e)[i] : ((const int*)e)[i];
}

__global__ void k_init(const void* edges, int n) {
    int i = blockIdx.x * blockDim.x + threadIdx.x;
    if (i < n) g_cnt[i] = 0;
    if (i == 0) {
        const long long* p = (const long long*)edges;
        int ok = 1;
        #pragma unroll
        for (int j = 0; j < 16; j++) {
            long long v = p[j];
            if (v < 0 || v >= NMAX) ok = 0;
        }
        g_idx64 = ok;
    }
}

__global__ void k_count(const void* __restrict__ edges, long long E) {
    long long i = (long long)blockIdx.x * blockDim.x + threadIdx.x;
    if (i < E) atomicAdd(&g_cnt[edge_at(edges, E + i, g_idx64)], 1);
}

__global__ void __launch_bounds__(1024) k_scan1(int n) {
    __shared__ int sm[1024];
    int t = threadIdx.x;
    int i = blockIdx.x * 1024 + t;
    int v = (i < n) ? g_cnt[i] : 0;
    sm[t] = v;
    __syncthreads();
    #pragma unroll
    for (int o = 1; o < 1024; o <<= 1) {
        int u = (t >= o) ? sm[t - o] : 0;
        __syncthreads();
        sm[t] += u;
        __syncthreads();
    }
    if (i < n) g_scan[i] = sm[t];
    if (t == 1023) g_bsum[blockIdx.x] = sm[1023];
}

__global__ void k_scan2(int nb) {
    __shared__ int sm[128];
    int t = threadIdx.x;
    int v = (t < nb) ? g_bsum[t] : 0;
    sm[t] = v;
    __syncthreads();
    #pragma unroll
    for (int o = 1; o < 128; o <<= 1) {
        int u = (t >= o) ? sm[t - o] : 0;
        __syncthreads();
        sm[t] += u;
        __syncthreads();
    }
    if (t < nb) g_bsum[t] = sm[t] - v;
}

__global__ void __launch_bounds__(1024) k_scan3(int n, int E) {
    int i = blockIdx.x * 1024 + threadIdx.x;
    if (i < n) {
        int incl = g_scan[i] + g_bsum[blockIdx.x];
        int c = g_cnt[i];
        int off = incl - c;
        g_off[i] = off;
        g_cur[i] = off;
        g_dinv[i] = rsqrtf((float)(c + 1));
        if (i == n - 1) g_off[n] = E;
    }
}

__global__ void k_fill(const void* __restrict__ edges, long long E) {
    long long i = (long long)blockIdx.x * blockDim.x + threadIdx.x;
    if (i < E) {
        int is64 = g_idx64;
        int s = edge_at(edges, i, is64);
        int d = edge_at(edges, E + i, is64);
        g_csr[atomicAdd(&g_cur[d], 1)] = s;
    }
}

// ------------- W prep: W^T, split fp32 -> bf16 hi/lo, padded [n][k] -----------
__global__ void k_prepw(const float* __restrict__ W1, const float* __restrict__ W2,
                        const float* __restrict__ W3) {
    int idx = blockIdx.x * blockDim.x + threadIdx.x;
    if (idx >= 16384 * 2 + 8192) return;
    int layer, nout, e;
    const float* W;
    if (idx < 16384)       { layer = 0; nout = 128; e = idx;         W = W1; }
    else if (idx < 32768)  { layer = 1; nout = 128; e = idx - 16384; W = W2; }
    else                   { layer = 2; nout = 64;  e = idx - 32768; W = W3; }
    int k = e / nout, nn = e % nout;
    float w = W[k * nout + nn];
    __nv_bfloat16 hi = __float2bfloat16(w);
    __nv_bfloat16 lo = __float2bfloat16(w - __bfloat162float(hi));
    uint32_t off = (uint32_t)(nn * 136 + k) * 2;
    *(__nv_bfloat16*)&g_wt[layer][0][off] = hi;
    *(__nv_bfloat16*)&g_wt[layer][1][off] = lo;
}

// ------------- HMMA GEMM: g_buf[r] = dinv[r] * (X @ W)[r] ----------------------
__device__ __forceinline__ void lm_x4(uint32_t& r0, uint32_t& r1, uint32_t& r2,
                                      uint32_t& r3, uint32_t a) {
    asm volatile("ldmatrix.sync.aligned.m8n8.x4.shared.b16 {%0,%1,%2,%3}, [%4];"
                 : "=r"(r0), "=r"(r1), "=r"(r2), "=r"(r3) : "r"(a));
}
__device__ __forceinline__ void lm_x2(uint32_t& r0, uint32_t& r1, uint32_t a) {
    asm volatile("ldmatrix.sync.aligned.m8n8.x2.shared.b16 {%0,%1}, [%2];"
                 : "=r"(r0), "=r"(r1) : "r"(a));
}
__device__ __forceinline__ void mma_bf16(float* c, uint32_t a0, uint32_t a1,
                                         uint32_t a2, uint32_t a3,
                                         uint32_t b0, uint32_t b1) {
    asm volatile("mma.sync.aligned.m16n8k16.row.col.f32.bf16.bf16.f32 "
                 "{%0,%1,%2,%3}, {%4,%5,%6,%7}, {%8,%9}, {%0,%1,%2,%3};"
                 : "+f"(c[0]), "+f"(c[1]), "+f"(c[2]), "+f"(c[3])
                 : "r"(a0), "r"(a1), "r"(a2), "r"(a3), "r"(b0), "r"(b1));
}

template<int NOUT, bool RELU>
__global__ void __launch_bounds__(256) k_hgemm(const float* __restrict__ X,
                                               int layer, int n) {
    extern __shared__ char sm[];
    constexpr int BSZ = NOUT * 272;
    constexpr int B_HI = 0;
    constexpr int B_LO = BSZ;
    constexpr int A_HI = 2 * BSZ;
    constexpr int A_LO = 2 * BSZ + 128 * 272;
    const int t = threadIdx.x;
    const int row0 = blockIdx.x * 128;

    uint32_t sb;
    asm("{ .reg .u64 u; cvta.to.shared.u64 u, %1; cvt.u32.u64 %0, u; }"
        : "=r"(sb) : "l"(sm));

    {
        const float4* s0 = (const float4*)&g_wt[layer][0][0];
        const float4* s1 = (const float4*)&g_wt[layer][1][0];
        float4* d0 = (float4*)(sm + B_HI);
        float4* d1 = (float4*)(sm + B_LO);
        #pragma unroll
        for (int i = t; i < BSZ / 16; i += 256) { d0[i] = s0[i]; d1[i] = s1[i]; }
    }

    {
        const int row = t >> 1;
        const int c0 = (t & 1) * 64;
        const int gr = row0 + row;
        const float4* xr = (const float4*)(X + (size_t)gr * 128 + c0);
        char* ah = sm + A_HI + row * 272 + c0 * 2;
        char* al = sm + A_LO + row * 272 + c0 * 2;
        #pragma unroll 4
        for (int q = 0; q < 16; q++) {
            float4 v = (gr < n) ? xr[q] : make_float4(0.f, 0.f, 0.f, 0.f);
            if (RELU) {
                v.x = fmaxf(v.x, 0.f); v.y = fmaxf(v.y, 0.f);
                v.z = fmaxf(v.z, 0.f); v.w = fmaxf(v.w, 0.f);
            }
            __nv_bfloat162 h0, h1, l0, l1;
            h0.x = __float2bfloat16(v.x); h0.y = __float2bfloat16(v.y);
            h1.x = __float2bfloat16(v.z); h1.y = __float2bfloat16(v.w);
            l0.x = __float2bfloat16(v.x - __bfloat162float(h0.x));
            l0.y = __float2bfloat16(v.y - __bfloat162float(h0.y));
            l1.x = __float2bfloat16(v.z - __bfloat162float(h1.x));
            l1.y = __float2bfloat16(v.w - __bfloat162float(h1.y));
            *(__nv_bfloat162*)(ah + q * 8)     = h0;
            *(__nv_bfloat162*)(ah + q * 8 + 4) = h1;
            *(__nv_bfloat162*)(al + q * 8)     = l0;
            *(__nv_bfloat162*)(al + q * 8 + 4) = l1;
        }
    }
    __syncthreads();

    const int warp = t >> 5, lane = t & 31;
    constexpr int NCH = NOUT / 8;
    float acc[NCH][4];
    #pragma unroll
    for (int nc = 0; nc < NCH; nc++)
        #pragma unroll
        for (int q = 0; q < 4; q++) acc[nc][q] = 0.f;

    const uint32_t aRow = sb + A_HI
        + (uint32_t)(warp * 16 + (lane & 7) + ((lane >> 3) & 1) * 8) * 272
        + (lane >> 4) * 16;
    const int bl = lane & 15;
    const uint32_t bRow = sb + B_HI + (uint32_t)(bl & 7) * 272 + ((bl >> 3) & 1) * 16;

    #pragma unroll
    for (int kc = 0; kc < 8; kc++) {
        uint32_t ah0, ah1, ah2, ah3, al0, al1, al2, al3;
        lm_x4(ah0, ah1, ah2, ah3, aRow + kc * 32);
        lm_x4(al0, al1, al2, al3, aRow + kc * 32 + (A_LO - A_HI));
        #pragma unroll
        for (int nc = 0; nc < NCH; nc++) {
            uint32_t bh0, bh1, bl0, bl1;
            uint32_t ba = bRow + (uint32_t)nc * 8 * 272 + kc * 32;
            lm_x2(bh0, bh1, ba);
            lm_x2(bl0, bl1, ba + BSZ);
            mma_bf16(acc[nc], ah0, ah1, ah2, ah3, bh0, bh1);
            mma_bf16(acc[nc], ah0, ah1, ah2, ah3, bl0, bl1);
            mma_bf16(acc[nc], al0, al1, al2, al3, bh0, bh1);
        }
    }

    {
        const int r0 = row0 + warp * 16 + (lane >> 2);
        const int r1 = r0 + 8;
        const int cb = (lane & 3) * 2;
        const float dv0 = (r0 < n) ? g_dinv[r0] : 0.f;
        const float dv1 = (r1 < n) ? g_dinv[r1] : 0.f;
        #pragma unroll
        for (int nc = 0; nc < NCH; nc++) {
            int col = nc * 8 + cb;
            if (r0 < n) {
                float2 o; o.x = dv0 * acc[nc][0]; o.y = dv0 * acc[nc][1];
                *(float2*)(g_buf + (size_t)r0 * NOUT + col) = o;
            }
            if (r1 < n) {
                float2 o; o.x = dv1 * acc[nc][2]; o.y = dv1 * acc[nc][3];
                *(float2*)(g_buf + (size_t)r1 * NOUT + col) = o;
            }
        }
    }
}

// ---------------- CSR gather: e[d] = dd*(self + sum_s buf[s]) + b --------------
__global__ void k_gather128(const float* __restrict__ bias,
                            float* __restrict__ e, int n) {
    int w = (blockIdx.x * blockDim.x + threadIdx.x) >> 5;
    int lane = threadIdx.x & 31;
    if (w >= n) return;
    int j = g_off[w], end = g_off[w + 1];
    float dd = g_dinv[w];
    float4 a0 = *(const float4*)(g_buf + (size_t)w * 128 + lane * 4);
    float4 a1 = make_float4(0.f, 0.f, 0.f, 0.f);
    float4 a2 = make_float4(0.f, 0.f, 0.f, 0.f);
    float4 a3 = make_float4(0.f, 0.f, 0.f, 0.f);
    for (; j + 8 <= end; j += 8) {
        int s0 = __ldg(&g_csr[j]);
        int s1 = __ldg(&g_csr[j + 1]);
        int s2 = __ldg(&g_csr[j + 2]);
        int s3 = __ldg(&g_csr[j + 3]);
        int s4 = __ldg(&g_csr[j + 4]);
        int s5 = __ldg(&g_csr[j + 5]);
        int s6 = __ldg(&g_csr[j + 6]);
        int s7 = __ldg(&g_csr[j + 7]);
        float4 v0 = *(const float4*)(g_buf + (size_t)s0 * 128 + lane * 4);
        float4 v1 = *(const float4*)(g_buf + (size_t)s1 * 128 + lane * 4);
        float4 v2 = *(const float4*)(g_buf + (size_t)s2 * 128 + lane * 4);
        float4 v3 = *(const float4*)(g_buf + (size_t)s3 * 128 + lane * 4);
        float4 v4 = *(const float4*)(g_buf + (size_t)s4 * 128 + lane * 4);
        float4 v5 = *(const float4*)(g_buf + (size_t)s5 * 128 + lane * 4);
        float4 v6 = *(const float4*)(g_buf + (size_t)s6 * 128 + lane * 4);
        float4 v7 = *(const float4*)(g_buf + (size_t)s7 * 128 + lane * 4);
        a0.x += v0.x + v4.x; a0.y += v0.y + v4.y; a0.z += v0.z + v4.z; a0.w += v0.w + v4.w;
        a1.x += v1.x + v5.x; a1.y += v1.y + v5.y; a1.z += v1.z + v5.z; a1.w += v1.w + v5.w;
        a2.x += v2.x + v6.x; a2.y += v2.y + v6.y; a2.z += v2.z + v6.z; a2.w += v2.w + v6.w;
        a3.x += v3.x + v7.x; a3.y += v3.y + v7.y; a3.z += v3.z + v7.z; a3.w += v3.w + v7.w;
    }
    for (; j + 4 <= end; j += 4) {
        int s0 = __ldg(&g_csr[j]);
        int s1 = __ldg(&g_csr[j + 1]);
        int s2 = __ldg(&g_csr[j + 2]);
        int s3 = __ldg(&g_csr[j + 3]);
        float4 v0 = *(const float4*)(g_buf + (size_t)s0 * 128 + lane * 4);
        float4 v1 = *(const float4*)(g_buf + (size_t)s1 * 128 + lane * 4);
        float4 v2 = *(const float4*)(g_buf + (size_t)s2 * 128 + lane * 4);
        float4 v3 = *(const float4*)(g_buf + (size_t)s3 * 128 + lane * 4);
        a0.x += v0.x; a0.y += v0.y; a0.z += v0.z; a0.w += v0.w;
        a1.x += v1.x; a1.y += v1.y; a1.z += v1.z; a1.w += v1.w;
        a2.x += v2.x; a2.y += v2.y; a2.z += v2.z; a2.w += v2.w;
        a3.x += v3.x; a3.y += v3.y; a3.z += v3.z; a3.w += v3.w;
    }
    for (; j < end; j++) {
        int s0 = __ldg(&g_csr[j]);
        float4 v0 = *(const float4*)(g_buf + (size_t)s0 * 128 + lane * 4);
        a0.x += v0.x; a0.y += v0.y; a0.z += v0.z; a0.w += v0.w;
    }
    a0.x += a1.x + a2.x + a3.x;
    a0.y += a1.y + a2.y + a3.y;
    a0.z += a1.z + a2.z + a3.z;
    a0.w += a1.w + a2.w + a3.w;
    float4 bb = *(const float4*)(bias + lane * 4);
    float4 o;
    o.x = fmaf(dd, a0.x, bb.x); o.y = fmaf(dd, a0.y, bb.y);
    o.z = fmaf(dd, a0.z, bb.z); o.w = fmaf(dd, a0.w, bb.w);
    *(float4*)(e + (size_t)w * 128 + lane * 4) = o;
}

__global__ void k_gather64_lsm(const float* __restrict__ bias,
                               float* __restrict__ e3,
                               float* __restrict__ logp, int n) {
    int w = (blockIdx.x * blockDim.x + threadIdx.x) >> 5;
    int lane = threadIdx.x & 31;
    if (w >= n) return;
    int j = g_off[w], end = g_off[w + 1];
    float dd = g_dinv[w];
    float2 a0 = *(const float2*)(g_buf + (size_t)w * 64 + lane * 2);
    float2 a1 = make_float2(0.f, 0.f);
    float2 a2 = make_float2(0.f, 0.f);
    float2 a3 = make_float2(0.f, 0.f);
    for (; j + 8 <= end; j += 8) {
        int s0 = __ldg(&g_csr[j]);
        int s1 = __ldg(&g_csr[j + 1]);
        int s2 = __ldg(&g_csr[j + 2]);
        int s3 = __ldg(&g_csr[j + 3]);
        int s4 = __ldg(&g_csr[j + 4]);
        int s5 = __ldg(&g_csr[j + 5]);
        int s6 = __ldg(&g_csr[j + 6]);
        int s7 = __ldg(&g_csr[j + 7]);
        float2 v0 = *(const float2*)(g_buf + (size_t)s0 * 64 + lane * 2);
        float2 v1 = *(const float2*)(g_buf + (size_t)s1 * 64 + lane * 2);
        float2 v2 = *(const float2*)(g_buf + (size_t)s2 * 64 + lane * 2);
        float2 v3 = *(const float2*)(g_buf + (size_t)s3 * 64 + lane * 2);
        float2 v4 = *(const float2*)(g_buf + (size_t)s4 * 64 + lane * 2);
        float2 v5 = *(const float2*)(g_buf + (size_t)s5 * 64 + lane * 2);
        float2 v6 = *(const float2*)(g_buf + (size_t)s6 * 64 + lane * 2);
        float2 v7 = *(const float2*)(g_buf + (size_t)s7 * 64 + lane * 2);
        a0.x += v0.x + v4.x; a0.y += v0.y + v4.y;
        a1.x += v1.x + v5.x; a1.y += v1.y + v5.y;
        a2.x += v2.x + v6.x; a2.y += v2.y + v6.y;
        a3.x += v3.x + v7.x; a3.y += v3.y + v7.y;
    }
    for (; j + 4 <= end; j += 4) {
        int s0 = __ldg(&g_csr[j]);
        int s1 = __ldg(&g_csr[j + 1]);
        int s2 = __ldg(&g_csr[j + 2]);
        int s3 = __ldg(&g_csr[j + 3]);
        float2 v0 = *(const float2*)(g_buf + (size_t)s0 * 64 + lane * 2);
        float2 v1 = *(const float2*)(g_buf + (size_t)s1 * 64 + lane * 2);
        float2 v2 = *(const float2*)(g_buf + (size_t)s2 * 64 + lane * 2);
        float2 v3 = *(const float2*)(g_buf + (size_t)s3 * 64 + lane * 2);
        a0.x += v0.x; a0.y += v0.y;
        a1.x += v1.x; a1.y += v1.y;
        a2.x += v2.x; a2.y += v2.y;
        a3.x += v3.x; a3.y += v3.y;
    }
    for (; j < end; j++) {
        int s0 = __ldg(&g_csr[j]);
        float2 v0 = *(const float2*)(g_buf + (size_t)s0 * 64 + lane * 2);
        a0.x += v0.x; a0.y += v0.y;
    }
    a0.x += a1.x + a2.x + a3.x;
    a0.y += a1.y + a2.y + a3.y;
    float2 bb = *(const float2*)(bias + lane * 2);
    float r0 = fmaf(dd, a0.x, bb.x);
    float r1 = fmaf(dd, a0.y, bb.y);
    float2 ev; ev.x = r0; ev.y = r1;
    *(float2*)(e3 + (size_t)w * 64 + lane * 2) = ev;
    float mx = fmaxf(r0, r1);
    #pragma unroll
    for (int o = 16; o; o >>= 1) mx = fmaxf(mx, __shfl_xor_sync(0xffffffffu, mx, o));
    float sum = expf(r0 - mx) + expf(r1 - mx);
    #pragma unroll
    for (int o = 16; o; o >>= 1) sum += __shfl_xor_sync(0xffffffffu, sum, o);
    float lz = mx + logf(sum);
    float2 lp; lp.x = r0 - lz; lp.y = r1 - lz;
    *(float2*)(logp + (size_t)w * 64 + lane * 2) = lp;
}

// ---------------- launcher ------------------------------------------------------
extern "C" void kernel_launch(void* const* d_in, const int* in_sizes, int n_in,
                              void* d_out, int out_size) {
    const float* x  = (const float*)d_in[0];
    const void*  ed = d_in[1];
    const float* W1 = (const float*)d_in[2];
    const float* b1 = (const float*)d_in[3];
    const float* W2 = (const float*)d_in[4];
    const float* b2 = (const float*)d_in[5];
    const float* W3 = (const float*)d_in[6];
    const float* b3 = (const float*)d_in[7];

    int       N = in_sizes[0] / DF;
    long long E = (long long)in_sizes[1] / 2;

    float* out  = (float*)d_out;
    float* logp = out;
    float* e1   = out + (size_t)N * NC;
    float* e2   = e1 + (size_t)N * DF;
    float* e3   = e2 + (size_t)N * DF;

    const int smem128 = 2 * 128 * 272 + 2 * 128 * 272;
    const int smem64  = 2 * 64 * 272 + 2 * 128 * 272;
    cudaFuncSetAttribute((const void*)k_hgemm<128, false>,
                         cudaFuncAttributeMaxDynamicSharedMemorySize, smem128);
    cudaFuncSetAttribute((const void*)k_hgemm<128, true>,
                         cudaFuncAttributeMaxDynamicSharedMemorySize, smem128);
    cudaFuncSetAttribute((const void*)k_hgemm<64, true>,
                         cudaFuncAttributeMaxDynamicSharedMemorySize, smem64);

    // lazily-created side stream + events for capture-forked CSR branch
    static cudaStream_t s_csr = nullptr;
    static cudaEvent_t ev_fork = nullptr, ev_join = nullptr;
    if (!s_csr) {
        cudaStreamCreateWithFlags(&s_csr, cudaStreamNonBlocking);
        cudaEventCreateWithFlags(&ev_fork, cudaEventDisableTiming);
        cudaEventCreateWithFlags(&ev_join, cudaEventDisableTiming);
    }

    int nb_nodes = (N + 255) / 256;
    int nb_edges = (int)((E + 255) / 256);
    int nb_scan  = (N + 1023) / 1024;
    int nb_gemm  = (N + 127) / 128;
    int nb_gat   = (N + 7) / 8;

    // ---- fork: CSR chain on s_csr, W-prep + GEMM1 on main ----
    cudaEventRecord(ev_fork, 0);
    cudaStreamWaitEvent(s_csr, ev_fork, 0);

    k_init<<<nb_nodes, 256, 0, s_csr>>>(ed, N);
    k_count<<<nb_edges, 256, 0, s_csr>>>(ed, E);
    k_scan1<<<nb_scan, 1024, 0, s_csr>>>(N);
    k_scan2<<<1, 128, 0, s_csr>>>(nb_scan);
    k_scan3<<<nb_scan, 1024, 0, s_csr>>>(N, (int)E);
    k_fill<<<nb_edges, 256, 0, s_csr>>>(ed, E);
    cudaEventRecord(ev_join, s_csr);

    k_prepw<<<(16384 * 2 + 8192 + 255) / 256, 256>>>(W1, W2, W3);

    // GEMM1 needs g_dinv (from k_scan3). Its epilogue scaling depends on the
    // CSR branch, so join before GEMM1.
    cudaStreamWaitEvent(0, ev_join, 0);

    // ---- layer 1 ----
    k_hgemm<128, false><<<nb_gemm, 256, smem128>>>(x, 0, N);
    k_gather128<<<nb_gat, 256>>>(b1, e1, N);

    // ---- layer 2 (relu fused into A conversion) ----
    k_hgemm<128, true><<<nb_gemm, 256, smem128>>>(e1, 1, N);
    k_gather128<<<nb_gat, 256>>>(b2, e2, N);

    // ---- layer 3 + fused log_softmax ----
    k_hgemm<64, true><<<nb_gemm, 256, smem64>>>(e2, 2, N);
    k_gather64_lsm<<<nb_gat, 256>>>(b3, e3, logp, N);
}

// round 7
// speedup vs baseline: 1.0374x; 1.0374x over previous
#include <cuda_runtime.h>
#include <cuda_bf16.h>
#include <cuda_fp16.h>
#include <cstdint>
#include <cstddef>

#define NMAX 50000
#define EMAX 800000
#define DF   128
#define NC   64

// ---------------- scratch (static device globals; no allocation) -------------
__device__ float  g_dinv[NMAX];
__device__ float  g_buf[(size_t)NMAX * DF];    // fp32: self-term + exactness
__device__ __half g_bufh[(size_t)NMAX * DF];   // fp16 mirror for neighbor gather
__device__ int    g_cnt[NMAX];
__device__ int    g_scan[NMAX];
__device__ int    g_bsum[128];
__device__ int    g_off[NMAX + 1];
__device__ int    g_cur[NMAX];
__device__ int    g_csr[EMAX];
__device__ int    g_idx64;
// W^T split to bf16 hi/lo, padded layout [n*136 + k] halves: [layer][hi/lo]
__device__ __align__(16) unsigned char g_wt[3][2][128 * 272];

// ---------------- edge utils ---------------------------------------------------
__device__ __forceinline__ int edge_at(const void* e, long long i, int is64) {
    return is64 ? (int)((const long long*)e)[i] : ((const int*)e)[i];
}

__global__ void k_init(const void* edges, int n) {
    int i = blockIdx.x * blockDim.x + threadIdx.x;
    if (i < n) g_cnt[i] = 0;
    if (i == 0) {
        const long long* p = (const long long*)edges;
        int ok = 1;
        #pragma unroll
        for (int j = 0; j < 16; j++) {
            long long v = p[j];
            if (v < 0 || v >= NMAX) ok = 0;
        }
        g_idx64 = ok;
    }
}

__global__ void k_count(const void* __restrict__ edges, long long E) {
    long long i = (long long)blockIdx.x * blockDim.x + threadIdx.x;
    if (i < E) atomicAdd(&g_cnt[edge_at(edges, E + i, g_idx64)], 1);
}

__global__ void __launch_bounds__(1024) k_scan1(int n) {
    __shared__ int sm[1024];
    int t = threadIdx.x;
    int i = blockIdx.x * 1024 + t;
    int v = (i < n) ? g_cnt[i] : 0;
    sm[t] = v;
    __syncthreads();
    #pragma unroll
    for (int o = 1; o < 1024; o <<= 1) {
        int u = (t >= o) ? sm[t - o] : 0;
        __syncthreads();
        sm[t] += u;
        __syncthreads();
    }
    if (i < n) g_scan[i] = sm[t];
    if (t == 1023) g_bsum[blockIdx.x] = sm[1023];
}

__global__ void k_scan2(int nb) {
    __shared__ int sm[128];
    int t = threadIdx.x;
    int v = (t < nb) ? g_bsum[t] : 0;
    sm[t] = v;
    __syncthreads();
    #pragma unroll
    for (int o = 1; o < 128; o <<= 1) {
        int u = (t >= o) ? sm[t - o] : 0;
        __syncthreads();
        sm[t] += u;
        __syncthreads();
    }
    if (t < nb) g_bsum[t] = sm[t] - v;
}

__global__ void __launch_bounds__(1024) k_scan3(int n, int E) {
    int i = blockIdx.x * 1024 + threadIdx.x;
    if (i < n) {
        int incl = g_scan[i] + g_bsum[blockIdx.x];
        int c = g_cnt[i];
        int off = incl - c;
        g_off[i] = off;
        g_cur[i] = off;
        g_dinv[i] = rsqrtf((float)(c + 1));
        if (i == n - 1) g_off[n] = E;
    }
}

__global__ void k_fill(const void* __restrict__ edges, long long E) {
    long long i = (long long)blockIdx.x * blockDim.x + threadIdx.x;
    if (i < E) {
        int is64 = g_idx64;
        int s = edge_at(edges, i, is64);
        int d = edge_at(edges, E + i, is64);
        g_csr[atomicAdd(&g_cur[d], 1)] = s;
    }
}

// ------------- W prep: W^T, split fp32 -> bf16 hi/lo, padded [n][k] -----------
__global__ void k_prepw(const float* __restrict__ W1, const float* __restrict__ W2,
                        const float* __restrict__ W3) {
    int idx = blockIdx.x * blockDim.x + threadIdx.x;
    if (idx >= 16384 * 2 + 8192) return;
    int layer, nout, e;
    const float* W;
    if (idx < 16384)       { layer = 0; nout = 128; e = idx;         W = W1; }
    else if (idx < 32768)  { layer = 1; nout = 128; e = idx - 16384; W = W2; }
    else                   { layer = 2; nout = 64;  e = idx - 32768; W = W3; }
    int k = e / nout, nn = e % nout;
    float w = W[k * nout + nn];
    __nv_bfloat16 hi = __float2bfloat16(w);
    __nv_bfloat16 lo = __float2bfloat16(w - __bfloat162float(hi));
    uint32_t off = (uint32_t)(nn * 136 + k) * 2;
    *(__nv_bfloat16*)&g_wt[layer][0][off] = hi;
    *(__nv_bfloat16*)&g_wt[layer][1][off] = lo;
}

// ------------- HMMA GEMM: g_buf[r] = dinv[r] * (X @ W)[r]  (+ fp16 mirror) -----
__device__ __forceinline__ void lm_x4(uint32_t& r0, uint32_t& r1, uint32_t& r2,
                                      uint32_t& r3, uint32_t a) {
    asm volatile("ldmatrix.sync.aligned.m8n8.x4.shared.b16 {%0,%1,%2,%3}, [%4];"
                 : "=r"(r0), "=r"(r1), "=r"(r2), "=r"(r3) : "r"(a));
}
__device__ __forceinline__ void lm_x2(uint32_t& r0, uint32_t& r1, uint32_t a) {
    asm volatile("ldmatrix.sync.aligned.m8n8.x2.shared.b16 {%0,%1}, [%2];"
                 : "=r"(r0), "=r"(r1) : "r"(a));
}
__device__ __forceinline__ void mma_bf16(float* c, uint32_t a0, uint32_t a1,
                                         uint32_t a2, uint32_t a3,
                                         uint32_t b0, uint32_t b1) {
    asm volatile("mma.sync.aligned.m16n8k16.row.col.f32.bf16.bf16.f32 "
                 "{%0,%1,%2,%3}, {%4,%5,%6,%7}, {%8,%9}, {%0,%1,%2,%3};"
                 : "+f"(c[0]), "+f"(c[1]), "+f"(c[2]), "+f"(c[3])
                 : "r"(a0), "r"(a1), "r"(a2), "r"(a3), "r"(b0), "r"(b1));
}

template<int NOUT, bool RELU>
__global__ void __launch_bounds__(256) k_hgemm(const float* __restrict__ X,
                                               int layer, int n) {
    extern __shared__ char sm[];
    constexpr int BSZ = NOUT * 272;
    constexpr int B_HI = 0;
    constexpr int B_LO = BSZ;
    constexpr int A_HI = 2 * BSZ;
    constexpr int A_LO = 2 * BSZ + 128 * 272;
    const int t = threadIdx.x;
    const int row0 = blockIdx.x * 128;

    uint32_t sb;
    asm("{ .reg .u64 u; cvta.to.shared.u64 u, %1; cvt.u32.u64 %0, u; }"
        : "=r"(sb) : "l"(sm));

    {
        const float4* s0 = (const float4*)&g_wt[layer][0][0];
        const float4* s1 = (const float4*)&g_wt[layer][1][0];
        float4* d0 = (float4*)(sm + B_HI);
        float4* d1 = (float4*)(sm + B_LO);
        #pragma unroll
        for (int i = t; i < BSZ / 16; i += 256) { d0[i] = s0[i]; d1[i] = s1[i]; }
    }

    {
        const int row = t >> 1;
        const int c0 = (t & 1) * 64;
        const int gr = row0 + row;
        const float4* xr = (const float4*)(X + (size_t)gr * 128 + c0);
        char* ah = sm + A_HI + row * 272 + c0 * 2;
        char* al = sm + A_LO + row * 272 + c0 * 2;
        #pragma unroll 4
        for (int q = 0; q < 16; q++) {
            float4 v = (gr < n) ? xr[q] : make_float4(0.f, 0.f, 0.f, 0.f);
            if (RELU) {
                v.x = fmaxf(v.x, 0.f); v.y = fmaxf(v.y, 0.f);
                v.z = fmaxf(v.z, 0.f); v.w = fmaxf(v.w, 0.f);
            }
            __nv_bfloat162 h0, h1, l0, l1;
            h0.x = __float2bfloat16(v.x); h0.y = __float2bfloat16(v.y);
            h1.x = __float2bfloat16(v.z); h1.y = __float2bfloat16(v.w);
            l0.x = __float2bfloat16(v.x - __bfloat162float(h0.x));
            l0.y = __float2bfloat16(v.y - __bfloat162float(h0.y));
            l1.x = __float2bfloat16(v.z - __bfloat162float(h1.x));
            l1.y = __float2bfloat16(v.w - __bfloat162float(h1.y));
            *(__nv_bfloat162*)(ah + q * 8)     = h0;
            *(__nv_bfloat162*)(ah + q * 8 + 4) = h1;
            *(__nv_bfloat162*)(al + q * 8)     = l0;
            *(__nv_bfloat162*)(al + q * 8 + 4) = l1;
        }
    }
    __syncthreads();

    const int warp = t >> 5, lane = t & 31;
    constexpr int NCH = NOUT / 8;
    float acc[NCH][4];
    #pragma unroll
    for (int nc = 0; nc < NCH; nc++)
        #pragma unroll
        for (int q = 0; q < 4; q++) acc[nc][q] = 0.f;

    const uint32_t aRow = sb + A_HI
        + (uint32_t)(warp * 16 + (lane & 7) + ((lane >> 3) & 1) * 8) * 272
        + (lane >> 4) * 16;
    const int bl = lane & 15;
    const uint32_t bRow = sb + B_HI + (uint32_t)(bl & 7) * 272 + ((bl >> 3) & 1) * 16;

    #pragma unroll
    for (int kc = 0; kc < 8; kc++) {
        uint32_t ah0, ah1, ah2, ah3, al0, al1, al2, al3;
        lm_x4(ah0, ah1, ah2, ah3, aRow + kc * 32);
        lm_x4(al0, al1, al2, al3, aRow + kc * 32 + (A_LO - A_HI));
        #pragma unroll
        for (int nc = 0; nc < NCH; nc++) {
            uint32_t bh0, bh1, bl0, bl1;
            uint32_t ba = bRow + (uint32_t)nc * 8 * 272 + kc * 32;
            lm_x2(bh0, bh1, ba);
            lm_x2(bl0, bl1, ba + BSZ);
            mma_bf16(acc[nc], ah0, ah1, ah2, ah3, bh0, bh1);
            mma_bf16(acc[nc], ah0, ah1, ah2, ah3, bl0, bl1);
            mma_bf16(acc[nc], al0, al1, al2, al3, bh0, bh1);
        }
    }

    {
        const int r0 = row0 + warp * 16 + (lane >> 2);
        const int r1 = r0 + 8;
        const int cb = (lane & 3) * 2;
        const float dv0 = (r0 < n) ? g_dinv[r0] : 0.f;
        const float dv1 = (r1 < n) ? g_dinv[r1] : 0.f;
        #pragma unroll
        for (int nc = 0; nc < NCH; nc++) {
            int col = nc * 8 + cb;
            if (r0 < n) {
                float2 o; o.x = dv0 * acc[nc][0]; o.y = dv0 * acc[nc][1];
                *(float2*)(g_buf + (size_t)r0 * NOUT + col) = o;
                *(__half2*)(g_bufh + (size_t)r0 * NOUT + col) = __float22half2_rn(o);
            }
            if (r1 < n) {
                float2 o; o.x = dv1 * acc[nc][2]; o.y = dv1 * acc[nc][3];
                *(float2*)(g_buf + (size_t)r1 * NOUT + col) = o;
                *(__half2*)(g_bufh + (size_t)r1 * NOUT + col) = __float22half2_rn(o);
            }
        }
    }
}

// ------ CSR gather (fp16 neighbors, fp32 self): e[d] = dd*(self+sum) + b -------
__global__ void k_gather128(const float* __restrict__ bias,
                            float* __restrict__ e, int n) {
    int w = (blockIdx.x * blockDim.x + threadIdx.x) >> 5;
    int lane = threadIdx.x & 31;
    if (w >= n) return;
    int j = g_off[w], end = g_off[w + 1];
    float dd = g_dinv[w];
    // self term fp32 (lane covers cols [lane*4, lane*4+4))
    float4 a0 = *(const float4*)(g_buf + (size_t)w * 128 + lane * 4);
    float4 a1 = make_float4(0.f, 0.f, 0.f, 0.f);
    float4 a2 = make_float4(0.f, 0.f, 0.f, 0.f);
    float4 a3 = make_float4(0.f, 0.f, 0.f, 0.f);
    for (; j + 4 <= end; j += 4) {
        int s0 = __ldg(&g_csr[j]);
        int s1 = __ldg(&g_csr[j + 1]);
        int s2 = __ldg(&g_csr[j + 2]);
        int s3 = __ldg(&g_csr[j + 3]);
        uint2 u0 = *(const uint2*)(g_bufh + (size_t)s0 * 128 + lane * 4);
        uint2 u1 = *(const uint2*)(g_bufh + (size_t)s1 * 128 + lane * 4);
        uint2 u2 = *(const uint2*)(g_bufh + (size_t)s2 * 128 + lane * 4);
        uint2 u3 = *(const uint2*)(g_bufh + (size_t)s3 * 128 + lane * 4);
        float2 p;
        p = __half22float2(*(__half2*)&u0.x); a0.x += p.x; a0.y += p.y;
        p = __half22float2(*(__half2*)&u0.y); a0.z += p.x; a0.w += p.y;
        p = __half22float2(*(__half2*)&u1.x); a1.x += p.x; a1.y += p.y;
        p = __half22float2(*(__half2*)&u1.y); a1.z += p.x; a1.w += p.y;
        p = __half22float2(*(__half2*)&u2.x); a2.x += p.x; a2.y += p.y;
        p = __half22float2(*(__half2*)&u2.y); a2.z += p.x; a2.w += p.y;
        p = __half22float2(*(__half2*)&u3.x); a3.x += p.x; a3.y += p.y;
        p = __half22float2(*(__half2*)&u3.y); a3.z += p.x; a3.w += p.y;
    }
    for (; j < end; j++) {
        int s0 = __ldg(&g_csr[j]);
        uint2 u0 = *(const uint2*)(g_bufh + (size_t)s0 * 128 + lane * 4);
        float2 p;
        p = __half22float2(*(__half2*)&u0.x); a0.x += p.x; a0.y += p.y;
        p = __half22float2(*(__half2*)&u0.y); a0.z += p.x; a0.w += p.y;
    }
    a0.x += a1.x + a2.x + a3.x;
    a0.y += a1.y + a2.y + a3.y;
    a0.z += a1.z + a2.z + a3.z;
    a0.w += a1.w + a2.w + a3.w;
    float4 bb = *(const float4*)(bias + lane * 4);
    float4 o;
    o.x = fmaf(dd, a0.x, bb.x); o.y = fmaf(dd, a0.y, bb.y);
    o.z = fmaf(dd, a0.z, bb.z); o.w = fmaf(dd, a0.w, bb.w);
    *(float4*)(e + (size_t)w * 128 + lane * 4) = o;
}

__global__ void k_gather64_lsm(const float* __restrict__ bias,
                               float* __restrict__ e3,
                               float* __restrict__ logp, int n) {
    int w = (blockIdx.x * blockDim.x + threadIdx.x) >> 5;
    int lane = threadIdx.x & 31;
    if (w >= n) return;
    int j = g_off[w], end = g_off[w + 1];
    float dd = g_dinv[w];
    float2 a0 = *(const float2*)(g_buf + (size_t)w * 64 + lane * 2);  // self fp32
    float2 a1 = make_float2(0.f, 0.f);
    float2 a2 = make_float2(0.f, 0.f);
    float2 a3 = make_float2(0.f, 0.f);
    for (; j + 4 <= end; j += 4) {
        int s0 = __ldg(&g_csr[j]);
        int s1 = __ldg(&g_csr[j + 1]);
        int s2 = __ldg(&g_csr[j + 2]);
        int s3 = __ldg(&g_csr[j + 3]);
        uint32_t u0 = *(const uint32_t*)(g_bufh + (size_t)s0 * 64 + lane * 2);
        uint32_t u1 = *(const uint32_t*)(g_bufh + (size_t)s1 * 64 + lane * 2);
        uint32_t u2 = *(const uint32_t*)(g_bufh + (size_t)s2 * 64 + lane * 2);
        uint32_t u3 = *(const uint32_t*)(g_bufh + (size_t)s3 * 64 + lane * 2);
        float2 p;
        p = __half22float2(*(__half2*)&u0); a0.x += p.x; a0.y += p.y;
        p = __half22float2(*(__half2*)&u1); a1.x += p.x; a1.y += p.y;
        p = __half22float2(*(__half2*)&u2); a2.x += p.x; a2.y += p.y;
        p = __half22float2(*(__half2*)&u3); a3.x += p.x; a3.y += p.y;
    }
    for (; j < end; j++) {
        int s0 = __ldg(&g_csr[j]);
        uint32_t u0 = *(const uint32_t*)(g_bufh + (size_t)s0 * 64 + lane * 2);
        float2 p = __half22float2(*(__half2*)&u0);
        a0.x += p.x; a0.y += p.y;
    }
    a0.x += a1.x + a2.x + a3.x;
    a0.y += a1.y + a2.y + a3.y;
    float2 bb = *(const float2*)(bias + lane * 2);
    float r0 = fmaf(dd, a0.x, bb.x);
    float r1 = fmaf(dd, a0.y, bb.y);
    float2 ev; ev.x = r0; ev.y = r1;
    *(float2*)(e3 + (size_t)w * 64 + lane * 2) = ev;
    float mx = fmaxf(r0, r1);
    #pragma unroll
    for (int o = 16; o; o >>= 1) mx = fmaxf(mx, __shfl_xor_sync(0xffffffffu, mx, o));
    float sum = expf(r0 - mx) + expf(r1 - mx);
    #pragma unroll
    for (int o = 16; o; o >>= 1) sum += __shfl_xor_sync(0xffffffffu, sum, o);
    float lz = mx + logf(sum);
    float2 lp; lp.x = r0 - lz; lp.y = r1 - lz;
    *(float2*)(logp + (size_t)w * 64 + lane * 2) = lp;
}

// ---------------- launcher ------------------------------------------------------
extern "C" void kernel_launch(void* const* d_in, const int* in_sizes, int n_in,
                              void* d_out, int out_size) {
    const float* x  = (const float*)d_in[0];
    const void*  ed = d_in[1];
    const float* W1 = (const float*)d_in[2];
    const float* b1 = (const float*)d_in[3];
    const float* W2 = (const float*)d_in[4];
    const float* b2 = (const float*)d_in[5];
    const float* W3 = (const float*)d_in[6];
    const float* b3 = (const float*)d_in[7];

    int       N = in_sizes[0] / DF;
    long long E = (long long)in_sizes[1] / 2;

    float* out  = (float*)d_out;
    float* logp = out;
    float* e1   = out + (size_t)N * NC;
    float* e2   = e1 + (size_t)N * DF;
    float* e3   = e2 + (size_t)N * DF;

    const int smem128 = 2 * 128 * 272 + 2 * 128 * 272;
    const int smem64  = 2 * 64 * 272 + 2 * 128 * 272;
    cudaFuncSetAttribute((const void*)k_hgemm<128, false>,
                         cudaFuncAttributeMaxDynamicSharedMemorySize, smem128);
    cudaFuncSetAttribute((const void*)k_hgemm<128, true>,
                         cudaFuncAttributeMaxDynamicSharedMemorySize, smem128);
    cudaFuncSetAttribute((const void*)k_hgemm<64, true>,
                         cudaFuncAttributeMaxDynamicSharedMemorySize, smem64);

    int nb_nodes = (N + 255) / 256;
    int nb_edges = (int)((E + 255) / 256);
    int nb_scan  = (N + 1023) / 1024;
    int nb_gemm  = (N + 127) / 128;
    int nb_gat   = (N + 7) / 8;

    // ---- CSR build + W prep (single stream; fork regressed in R6) ----
    k_init<<<nb_nodes, 256>>>(ed, N);
    k_prepw<<<(16384 * 2 + 8192 + 255) / 256, 256>>>(W1, W2, W3);
    k_count<<<nb_edges, 256>>>(ed, E);
    k_scan1<<<nb_scan, 1024>>>(N);
    k_scan2<<<1, 128>>>(nb_scan);
    k_scan3<<<nb_scan, 1024>>>(N, (int)E);
    k_fill<<<nb_edges, 256>>>(ed, E);

    // ---- layer 1 ----
    k_hgemm<128, false><<<nb_gemm, 256, smem128>>>(x, 0, N);
    k_gather128<<<nb_gat, 256>>>(b1, e1, N);

    // ---- layer 2 (relu fused into A conversion) ----
    k_hgemm<128, true><<<nb_gemm, 256, smem128>>>(e1, 1, N);
    k_gather128<<<nb_gat, 256>>>(b2, e2, N);

    // ---- layer 3 + fused log_softmax ----
    k_hgemm<64, true><<<nb_gemm, 256, smem64>>>(e2, 2, N);
    k_gather64_lsm<<<nb_gat, 256>>>(b3, e3, logp, N);
}